// round 1
// baseline (speedup 1.0000x reference)
#include <cuda_runtime.h>

#define BT 256

__global__ __launch_bounds__(256, 2) void convintnet_kernel(
    const float* __restrict__ x,
    const float* __restrict__ bn_gamma, const float* __restrict__ bn_beta,
    const float* __restrict__ bn_mean, const float* __restrict__ bn_var,
    const float* __restrict__ eW1, const float* __restrict__ eb1,
    const float* __restrict__ eW2, const float* __restrict__ eb2,
    const float* __restrict__ eW3, const float* __restrict__ eb3,
    const float* __restrict__ dW1, const float* __restrict__ db1,
    const float* __restrict__ dW2, const float* __restrict__ db2,
    const float* __restrict__ dW3, const float* __restrict__ db3,
    const float* __restrict__ aW1, const float* __restrict__ ab1,
    const float* __restrict__ aW2, const float* __restrict__ ab2,
    float* __restrict__ out)
{
    // ---- shared memory ----
    __shared__ float s_xn[800];            // [50][16] normalized input
    __shared__ float s_AB[3000];           // A=[50][30], B=[50][30]; reused as d1=[50][45]
    __shared__ float s_eff[300];           // [50][6] scatter-summed effects
    __shared__ float s_d2[1100];           // [50][22]
    __shared__ float s_W1a[480], s_W1b[480], s_eb1[30];
    __shared__ float s_W2[480];            // padded [30][16] (col 15 = 0)
    __shared__ float s_b2[16];             // padded (b2[15]=0)
    __shared__ float s_W3[128];            // padded [16][8] (row 15, cols 6..7 = 0)
    __shared__ float s_b3[8];              // padded
    __shared__ float s_dW1[990], s_db1[45];
    __shared__ float s_dW2[990], s_db2[22];
    __shared__ float s_dW3[132], s_db3[6];
    __shared__ float s_aW1[288], s_ab1[48];
    __shared__ float s_aW2[240], s_ab2[5];
    __shared__ float s_bns[16], s_bnt[16];
    __shared__ float s_dsum[6];
    __shared__ float s_a1[48];

    const int tid = threadIdx.x;
    const int b   = blockIdx.x;

    // ---- weight / param loads into smem ----
    for (int i = tid; i < 480; i += BT) s_W1a[i] = eW1[i];
    for (int i = tid; i < 480; i += BT) s_W1b[i] = eW1[480 + i];
    for (int i = tid; i < 480; i += BT) {
        int r = i >> 4, c = i & 15;
        s_W2[i] = (c < 15) ? eW2[r * 15 + c] : 0.f;
    }
    for (int i = tid; i < 128; i += BT) {
        int r = i >> 3, c = i & 7;
        s_W3[i] = (r < 15 && c < 6) ? eW3[r * 6 + c] : 0.f;
    }
    for (int i = tid; i < 990; i += BT) s_dW1[i] = dW1[i];
    for (int i = tid; i < 990; i += BT) s_dW2[i] = dW2[i];
    for (int i = tid; i < 132; i += BT) s_dW3[i] = dW3[i];
    for (int i = tid; i < 288; i += BT) s_aW1[i] = aW1[i];
    for (int i = tid; i < 240; i += BT) s_aW2[i] = aW2[i];
    if (tid < 30) s_eb1[tid] = eb1[tid];
    if (tid < 45) s_db1[tid] = db1[tid];
    if (tid < 22) s_db2[tid] = db2[tid];
    if (tid < 6)  s_db3[tid] = db3[tid];
    if (tid < 48) s_ab1[tid] = ab1[tid];
    if (tid < 5)  s_ab2[tid] = ab2[tid];
    if (tid < 16) {
        s_b2[tid] = (tid < 15) ? eb2[tid] : 0.f;
        float sc = bn_gamma[tid] * rsqrtf(bn_var[tid] + 1e-3f);
        s_bns[tid] = sc;
        s_bnt[tid] = bn_beta[tid] - bn_mean[tid] * sc;
    }
    if (tid < 8) s_b3[tid] = (tid < 6) ? eb3[tid] : 0.f;
    if (tid < 6) s_dsum[tid] = 0.f;
    for (int i = tid; i < 300; i += BT) s_eff[i] = 0.f;
    __syncthreads();

    // ---- batchnorm ----
    const float* xb = x + b * 800;
    for (int i = tid; i < 800; i += BT) {
        int f = i & 15;
        s_xn[i] = fmaf(xb[i], s_bns[f], s_bnt[f]);
    }
    __syncthreads();

    // ---- factored edge layer 1: A[n] = xn[n]@W1_top + eb1, B[n] = xn[n]@W1_bot ----
    for (int i = tid; i < 3000; i += BT) {
        int half = (i >= 1500);
        int idx  = half ? (i - 1500) : i;
        int n = idx / 30, k = idx - n * 30;
        const float* W = half ? s_W1b : s_W1a;
        float acc = half ? 0.f : s_eb1[k];
        const float* xr = s_xn + n * 16;
        #pragma unroll
        for (int f = 0; f < 16; f++) acc = fmaf(xr[f], W[f * 30 + k], acc);
        s_AB[i] = acc;
    }
    __syncthreads();

    // ---- edge MLP + receiver-grouped scatter ----
    // 250 threads: 5 threads per receiver r, each handling senders sub, sub+5, ...
    if (tid < 250) {
        int r = tid / 5, sub = tid - r * 5;
        const float* Ar = s_AB + r * 30;
        float acc0 = 0.f, acc1 = 0.f, acc2 = 0.f, acc3 = 0.f, acc4 = 0.f, acc5 = 0.f;
        for (int kk = sub; kk < 49; kk += 5) {
            int s = kk + (kk >= r);
            const float* Bs = s_AB + 1500 + s * 30;
            float h1[30];
            #pragma unroll
            for (int k = 0; k < 30; k++) h1[k] = fmaxf(Ar[k] + Bs[k], 0.f);
            float h2[16];
            #pragma unroll
            for (int j = 0; j < 16; j++) h2[j] = s_b2[j];
            #pragma unroll
            for (int i2 = 0; i2 < 30; i2++) {
                float v = h1[i2];
                #pragma unroll
                for (int j = 0; j < 16; j++)
                    h2[j] = fmaf(v, s_W2[i2 * 16 + j], h2[j]);
            }
            float h3[8];
            #pragma unroll
            for (int m = 0; m < 8; m++) h3[m] = s_b3[m];
            #pragma unroll
            for (int j = 0; j < 16; j++) {
                float v = fmaxf(h2[j], 0.f);
                #pragma unroll
                for (int m = 0; m < 8; m++)
                    h3[m] = fmaf(v, s_W3[j * 8 + m], h3[m]);
            }
            acc0 += fmaxf(h3[0], 0.f);
            acc1 += fmaxf(h3[1], 0.f);
            acc2 += fmaxf(h3[2], 0.f);
            acc3 += fmaxf(h3[3], 0.f);
            acc4 += fmaxf(h3[4], 0.f);
            acc5 += fmaxf(h3[5], 0.f);
        }
        atomicAdd(&s_eff[r * 6 + 0], acc0);
        atomicAdd(&s_eff[r * 6 + 1], acc1);
        atomicAdd(&s_eff[r * 6 + 2], acc2);
        atomicAdd(&s_eff[r * 6 + 3], acc3);
        atomicAdd(&s_eff[r * 6 + 4], acc4);
        atomicAdd(&s_eff[r * 6 + 5], acc5);
    }
    __syncthreads();

    // ---- dynamics MLP layer 1: ce=[xn, eff] (22) -> 45 ----
    float* s_d1 = s_AB;  // reuse (A/B dead after edge phase)
    for (int i = tid; i < 2250; i += BT) {
        int n = i / 45, o = i - n * 45;
        float acc = s_db1[o];
        const float* xr = s_xn + n * 16;
        #pragma unroll
        for (int f = 0; f < 16; f++) acc = fmaf(xr[f], s_dW1[f * 45 + o], acc);
        const float* er = s_eff + n * 6;
        #pragma unroll
        for (int m = 0; m < 6; m++) acc = fmaf(er[m], s_dW1[(16 + m) * 45 + o], acc);
        s_d1[i] = fmaxf(acc, 0.f);
    }
    __syncthreads();

    // ---- dynamics layer 2: 45 -> 22 ----
    for (int i = tid; i < 1100; i += BT) {
        int n = i / 22, o = i - n * 22;
        float acc = s_db2[o];
        const float* dr = s_d1 + n * 45;
        #pragma unroll
        for (int j = 0; j < 45; j++) acc = fmaf(dr[j], s_dW2[j * 22 + o], acc);
        s_d2[i] = fmaxf(acc, 0.f);
    }
    __syncthreads();

    // ---- dynamics layer 3: 22 -> 6, then sum over nodes ----
    for (int i = tid; i < 300; i += BT) {
        int n = i / 6, o = i - n * 6;
        float acc = s_db3[o];
        const float* dr = s_d2 + n * 22;
        #pragma unroll
        for (int j = 0; j < 22; j++) acc = fmaf(dr[j], s_dW3[j * 6 + o], acc);
        atomicAdd(&s_dsum[o], fmaxf(acc, 0.f));
    }
    __syncthreads();

    // ---- classifier layer 1: 6 -> 48 ----
    if (tid < 48) {
        float acc = s_ab1[tid];
        #pragma unroll
        for (int j = 0; j < 6; j++) acc = fmaf(s_dsum[j], s_aW1[j * 48 + tid], acc);
        s_a1[tid] = fmaxf(acc, 0.f);
    }
    __syncthreads();

    // ---- classifier layer 2 + softmax ----
    if (tid == 0) {
        float lg[5];
        #pragma unroll
        for (int o = 0; o < 5; o++) {
            float acc = s_ab2[o];
            #pragma unroll
            for (int j = 0; j < 48; j++) acc = fmaf(s_a1[j], s_aW2[j * 5 + o], acc);
            lg[o] = acc;
        }
        float mx = lg[0];
        #pragma unroll
        for (int o = 1; o < 5; o++) mx = fmaxf(mx, lg[o]);
        float e[5], sum = 0.f;
        #pragma unroll
        for (int o = 0; o < 5; o++) { e[o] = expf(lg[o] - mx); sum += e[o]; }
        float inv = 1.f / sum;
        #pragma unroll
        for (int o = 0; o < 5; o++) out[b * 5 + o] = e[o] * inv;
    }
}

extern "C" void kernel_launch(void* const* d_in, const int* in_sizes, int n_in,
                              void* d_out, int out_size) {
    const int B = in_sizes[0] / 800;  // x is [B, 50, 16]
    convintnet_kernel<<<B, BT>>>(
        (const float*)d_in[0],
        (const float*)d_in[1],  (const float*)d_in[2],
        (const float*)d_in[3],  (const float*)d_in[4],
        (const float*)d_in[5],  (const float*)d_in[6],
        (const float*)d_in[7],  (const float*)d_in[8],
        (const float*)d_in[9],  (const float*)d_in[10],
        (const float*)d_in[11], (const float*)d_in[12],
        (const float*)d_in[13], (const float*)d_in[14],
        (const float*)d_in[15], (const float*)d_in[16],
        (const float*)d_in[17], (const float*)d_in[18],
        (const float*)d_in[19], (const float*)d_in[20],
        (float*)d_out);
}

// round 2
// speedup vs baseline: 1.0891x; 1.0891x over previous
#include <cuda_runtime.h>

#define BT 256

typedef unsigned long long ull;

__device__ __forceinline__ ull pack2(float a, float b) {
    ull r;
    asm("mov.b64 %0, {%1, %2};" : "=l"(r) : "f"(a), "f"(b));
    return r;
}
__device__ __forceinline__ void unpack2(ull v, float& a, float& b) {
    asm("mov.b64 {%0, %1}, %2;" : "=f"(a), "=f"(b) : "l"(v));
}
__device__ __forceinline__ ull fma2(ull a, ull b, ull c) {
    ull d;
    asm("fma.rn.f32x2 %0, %1, %2, %3;" : "=l"(d) : "l"(a), "l"(b), "l"(c));
    return d;
}

__global__ __launch_bounds__(256, 2) void convintnet_kernel(
    const float* __restrict__ x,
    const float* __restrict__ bn_gamma, const float* __restrict__ bn_beta,
    const float* __restrict__ bn_mean, const float* __restrict__ bn_var,
    const float* __restrict__ eW1, const float* __restrict__ eb1,
    const float* __restrict__ eW2, const float* __restrict__ eb2,
    const float* __restrict__ eW3, const float* __restrict__ eb3,
    const float* __restrict__ dW1, const float* __restrict__ db1,
    const float* __restrict__ dW2, const float* __restrict__ db2,
    const float* __restrict__ dW3, const float* __restrict__ db3,
    const float* __restrict__ aW1, const float* __restrict__ ab1,
    const float* __restrict__ aW2, const float* __restrict__ ab2,
    float* __restrict__ out)
{
    // ---- shared memory ----
    __shared__ __align__(16) float s_xn[800];     // [50][16]
    __shared__ __align__(16) float s_buf[3100];   // A=[50] stride 31, B at +1550; reused as d1=[50][45]
    __shared__ __align__(16) float s_eff[304];    // [50][6] scatter-summed effects
    __shared__ __align__(16) float s_d2[1100];    // [50][22]
    __shared__ __align__(16) float s_W1a[480], s_W1b[480], s_eb1[32];
    __shared__ __align__(16) float s_W2[480];     // [30][16] (col 15 = 0)
    __shared__ __align__(16) float s_b2[16];      // b2[15]=0
    __shared__ __align__(16) float s_W3[96];      // [16][6] (row 15 = 0)
    __shared__ __align__(16) float s_b3[8];
    __shared__ __align__(16) float s_dW1[992], s_db1[48];
    __shared__ __align__(16) float s_dW2[992], s_db2[24];
    __shared__ __align__(16) float s_dW3[132], s_db3[8];
    __shared__ __align__(16) float s_aW1[288], s_ab1[48];
    __shared__ __align__(16) float s_aW2[240], s_ab2[8];
    __shared__ __align__(16) float s_bns[16], s_bnt[16];
    __shared__ __align__(16) float s_dsum[8];
    __shared__ __align__(16) float s_a1[48];

    const int tid = threadIdx.x;
    const int b   = blockIdx.x;

    // ---- params into smem ----
    for (int i = tid; i < 480; i += BT) s_W1a[i] = eW1[i];
    for (int i = tid; i < 480; i += BT) s_W1b[i] = eW1[480 + i];
    for (int i = tid; i < 480; i += BT) {
        int r = i >> 4, c = i & 15;
        s_W2[i] = (c < 15) ? eW2[r * 15 + c] : 0.f;
    }
    for (int i = tid; i < 96; i += BT) {
        int r = i / 6, c = i - r * 6;
        s_W3[i] = (r < 15) ? eW3[r * 6 + c] : 0.f;
    }
    for (int i = tid; i < 990; i += BT) s_dW1[i] = dW1[i];
    for (int i = tid; i < 990; i += BT) s_dW2[i] = dW2[i];
    for (int i = tid; i < 132; i += BT) s_dW3[i] = dW3[i];
    for (int i = tid; i < 288; i += BT) s_aW1[i] = aW1[i];
    for (int i = tid; i < 240; i += BT) s_aW2[i] = aW2[i];
    if (tid < 30) s_eb1[tid] = eb1[tid];
    if (tid < 45) s_db1[tid] = db1[tid];
    if (tid < 22) s_db2[tid] = db2[tid];
    if (tid < 6)  s_db3[tid] = db3[tid];
    if (tid < 48) s_ab1[tid] = ab1[tid];
    if (tid < 5)  s_ab2[tid] = ab2[tid];
    if (tid < 16) {
        s_b2[tid] = (tid < 15) ? eb2[tid] : 0.f;
        float sc = bn_gamma[tid] * rsqrtf(bn_var[tid] + 1e-3f);
        s_bns[tid] = sc;
        s_bnt[tid] = bn_beta[tid] - bn_mean[tid] * sc;
    }
    if (tid < 8) s_b3[tid] = (tid < 6) ? eb3[tid] : 0.f;
    if (tid < 8) s_dsum[tid] = 0.f;
    for (int i = tid; i < 304; i += BT) s_eff[i] = 0.f;
    __syncthreads();

    // ---- batchnorm ----
    const float* xb = x + b * 800;
    for (int i = tid; i < 800; i += BT) {
        int f = i & 15;
        s_xn[i] = fmaf(xb[i], s_bns[f], s_bnt[f]);
    }
    __syncthreads();

    // ---- factored edge layer 1: A[n]=xn[n]@W1_top+eb1, B[n]=xn[n]@W1_bot (row stride 31) ----
    for (int i = tid; i < 3000; i += BT) {
        int half = (i >= 1500);
        int idx  = half ? (i - 1500) : i;
        int n = idx / 30, k = idx - n * 30;
        const float* W = half ? s_W1b : s_W1a;
        float acc = half ? 0.f : s_eb1[k];
        const float* xr = s_xn + n * 16;
        #pragma unroll
        for (int f = 0; f < 16; f++) acc = fmaf(xr[f], W[f * 30 + k], acc);
        s_buf[(half ? 1550 : 0) + n * 31 + k] = acc;
    }
    __syncthreads();

    // ---- edge MLP + receiver-grouped scatter (packed f32x2) ----
    if (tid < 250) {
        const int r = tid / 5, sub = tid - r * 5;
        // cache receiver row A[r] in registers
        float arA[30];
        {
            const float* Ar = s_buf + r * 31;
            #pragma unroll
            for (int k = 0; k < 30; k++) arA[k] = Ar[k];
        }
        const ull* b2q = (const ull*)s_b2;   // 8 pairs
        const ull* b3q = (const ull*)s_b3;   // 3 pairs
        float acc[6];
        #pragma unroll
        for (int m = 0; m < 6; m++) acc[m] = 0.f;

        #pragma unroll 1
        for (int kk = sub; kk < 49; kk += 5) {
            int s = kk + (kk >= r);
            const float* Bs = s_buf + 1550 + s * 31;
            // layer 2: h2[16] pairs, relu(A+B) fused
            ull h2p[8];
            #pragma unroll
            for (int jp = 0; jp < 8; jp++) h2p[jp] = b2q[jp];
            #pragma unroll
            for (int i = 0; i < 30; i++) {
                float v = fmaxf(arA[i] + Bs[i], 0.f);
                ull vv = pack2(v, v);
                const ull* wq = (const ull*)(s_W2 + i * 16);
                #pragma unroll
                for (int jp = 0; jp < 8; jp++) h2p[jp] = fma2(vv, wq[jp], h2p[jp]);
            }
            // layer 3: 16 -> 6
            ull h3p[3];
            #pragma unroll
            for (int p = 0; p < 3; p++) h3p[p] = b3q[p];
            #pragma unroll
            for (int jp = 0; jp < 8; jp++) {
                float a, c;
                unpack2(h2p[jp], a, c);
                float va = fmaxf(a, 0.f), vc = fmaxf(c, 0.f);
                ull vva = pack2(va, va);
                const ull* w3a = (const ull*)(s_W3 + (2 * jp) * 6);
                #pragma unroll
                for (int p = 0; p < 3; p++) h3p[p] = fma2(vva, w3a[p], h3p[p]);
                ull vvc = pack2(vc, vc);
                const ull* w3c = (const ull*)(s_W3 + (2 * jp + 1) * 6);
                #pragma unroll
                for (int p = 0; p < 3; p++) h3p[p] = fma2(vvc, w3c[p], h3p[p]);
            }
            // relu + accumulate
            #pragma unroll
            for (int p = 0; p < 3; p++) {
                float a, c;
                unpack2(h3p[p], a, c);
                acc[2 * p]     += fmaxf(a, 0.f);
                acc[2 * p + 1] += fmaxf(c, 0.f);
            }
        }
        #pragma unroll
        for (int m = 0; m < 6; m++) atomicAdd(&s_eff[r * 6 + m], acc[m]);
    }
    __syncthreads();

    // ---- dynamics layer 1: [xn | eff] (22) -> 45 (reuse s_buf as d1) ----
    for (int i = tid; i < 2250; i += BT) {
        int n = i / 45, o = i - n * 45;
        float acc = s_db1[o];
        const float* xr = s_xn + n * 16;
        #pragma unroll
        for (int f = 0; f < 16; f++) acc = fmaf(xr[f], s_dW1[f * 45 + o], acc);
        const float* er = s_eff + n * 6;
        #pragma unroll
        for (int m = 0; m < 6; m++) acc = fmaf(er[m], s_dW1[(16 + m) * 45 + o], acc);
        s_buf[i] = fmaxf(acc, 0.f);
    }
    __syncthreads();

    // ---- dynamics layer 2: 45 -> 22 ----
    for (int i = tid; i < 1100; i += BT) {
        int n = i / 22, o = i - n * 22;
        float acc = s_db2[o];
        const float* dr = s_buf + n * 45;
        #pragma unroll
        for (int j = 0; j < 45; j++) acc = fmaf(dr[j], s_dW2[j * 22 + o], acc);
        s_d2[i] = fmaxf(acc, 0.f);
    }
    __syncthreads();

    // ---- dynamics layer 3: 22 -> 6, sum over nodes ----
    for (int i = tid; i < 300; i += BT) {
        int n = i / 6, o = i - n * 6;
        float acc = s_db3[o];
        const float* dr = s_d2 + n * 22;
        #pragma unroll
        for (int j = 0; j < 22; j++) acc = fmaf(dr[j], s_dW3[j * 6 + o], acc);
        atomicAdd(&s_dsum[o], fmaxf(acc, 0.f));
    }
    __syncthreads();

    // ---- classifier layer 1: 6 -> 48 ----
    if (tid < 48) {
        float acc = s_ab1[tid];
        #pragma unroll
        for (int j = 0; j < 6; j++) acc = fmaf(s_dsum[j], s_aW1[j * 48 + tid], acc);
        s_a1[tid] = fmaxf(acc, 0.f);
    }
    __syncthreads();

    // ---- classifier layer 2 + softmax ----
    if (tid == 0) {
        float lg[5];
        #pragma unroll
        for (int o = 0; o < 5; o++) {
            float acc = s_ab2[o];
            #pragma unroll
            for (int j = 0; j < 48; j++) acc = fmaf(s_a1[j], s_aW2[j * 5 + o], acc);
            lg[o] = acc;
        }
        float mx = lg[0];
        #pragma unroll
        for (int o = 1; o < 5; o++) mx = fmaxf(mx, lg[o]);
        float e[5], sum = 0.f;
        #pragma unroll
        for (int o = 0; o < 5; o++) { e[o] = expf(lg[o] - mx); sum += e[o]; }
        float inv = 1.f / sum;
        #pragma unroll
        for (int o = 0; o < 5; o++) out[b * 5 + o] = e[o] * inv;
    }
}

extern "C" void kernel_launch(void* const* d_in, const int* in_sizes, int n_in,
                              void* d_out, int out_size) {
    const int B = in_sizes[0] / 800;  // x is [B, 50, 16]
    convintnet_kernel<<<B, BT>>>(
        (const float*)d_in[0],
        (const float*)d_in[1],  (const float*)d_in[2],
        (const float*)d_in[3],  (const float*)d_in[4],
        (const float*)d_in[5],  (const float*)d_in[6],
        (const float*)d_in[7],  (const float*)d_in[8],
        (const float*)d_in[9],  (const float*)d_in[10],
        (const float*)d_in[11], (const float*)d_in[12],
        (const float*)d_in[13], (const float*)d_in[14],
        (const float*)d_in[15], (const float*)d_in[16],
        (const float*)d_in[17], (const float*)d_in[18],
        (const float*)d_in[19], (const float*)d_in[20],
        (float*)d_out);
}

// round 3
// speedup vs baseline: 6.5313x; 5.9970x over previous
#include <cuda_runtime.h>

#define BT 256

__global__ __launch_bounds__(256, 2) void convintnet_kernel(
    const float* __restrict__ x,
    const float* __restrict__ bn_gamma, const float* __restrict__ bn_beta,
    const float* __restrict__ bn_mean, const float* __restrict__ bn_var,
    const float* __restrict__ eW1, const float* __restrict__ eb1,
    const float* __restrict__ eW2, const float* __restrict__ eb2,
    const float* __restrict__ eW3, const float* __restrict__ eb3,
    const float* __restrict__ dW1, const float* __restrict__ db1,
    const float* __restrict__ dW2, const float* __restrict__ db2,
    const float* __restrict__ dW3, const float* __restrict__ db3,
    const float* __restrict__ aW1, const float* __restrict__ ab1,
    const float* __restrict__ aW2, const float* __restrict__ ab2,
    float* __restrict__ out)
{
    // ---- shared memory ----
    __shared__ __align__(16) float s_xn[800];     // [50][16]
    __shared__ __align__(16) float s_buf[3100];   // A=[50] stride 31; B at +1550; reused as d1=[50][45]
    __shared__ __align__(16) float s_eff[304];    // [50][6]
    __shared__ __align__(16) float s_d2[1100];    // [50][22]
    __shared__ __align__(16) float s_W1a[480], s_W1b[480], s_eb1[32];
    __shared__ __align__(16) float s_W2[480];     // [30][16] padded (col 15 = 0)
    __shared__ __align__(16) float s_b2[16];      // b2[15]=0
    __shared__ __align__(16) float s_W3[128];     // [16][8] padded (row 15, cols 6,7 = 0)
    __shared__ __align__(16) float s_b3[8];
    __shared__ __align__(16) float s_dW1[992], s_db1[48];
    __shared__ __align__(16) float s_dW2[992], s_db2[24];
    __shared__ __align__(16) float s_dW3[132], s_db3[8];
    __shared__ __align__(16) float s_aW1[288], s_ab1[48];
    __shared__ __align__(16) float s_aW2[240], s_ab2[8];
    __shared__ __align__(16) float s_bns[16], s_bnt[16];
    __shared__ __align__(16) float s_dsum[8];
    __shared__ __align__(16) float s_a1[48];

    const int tid = threadIdx.x;
    const int b   = blockIdx.x;

    // ---- params into smem ----
    for (int i = tid; i < 480; i += BT) s_W1a[i] = eW1[i];
    for (int i = tid; i < 480; i += BT) s_W1b[i] = eW1[480 + i];
    for (int i = tid; i < 480; i += BT) {
        int r = i >> 4, c = i & 15;
        s_W2[i] = (c < 15) ? eW2[r * 15 + c] : 0.f;
    }
    for (int i = tid; i < 128; i += BT) {
        int r = i >> 3, c = i & 7;
        s_W3[i] = (r < 15 && c < 6) ? eW3[r * 6 + c] : 0.f;
    }
    for (int i = tid; i < 990; i += BT) s_dW1[i] = dW1[i];
    for (int i = tid; i < 990; i += BT) s_dW2[i] = dW2[i];
    for (int i = tid; i < 132; i += BT) s_dW3[i] = dW3[i];
    for (int i = tid; i < 288; i += BT) s_aW1[i] = aW1[i];
    for (int i = tid; i < 240; i += BT) s_aW2[i] = aW2[i];
    if (tid < 30) s_eb1[tid] = eb1[tid];
    if (tid < 45) s_db1[tid] = db1[tid];
    if (tid < 22) s_db2[tid] = db2[tid];
    if (tid < 6)  s_db3[tid] = db3[tid];
    if (tid < 48) s_ab1[tid] = ab1[tid];
    if (tid < 5)  s_ab2[tid] = ab2[tid];
    if (tid < 16) {
        s_b2[tid] = (tid < 15) ? eb2[tid] : 0.f;
        float sc = bn_gamma[tid] * rsqrtf(bn_var[tid] + 1e-3f);
        s_bns[tid] = sc;
        s_bnt[tid] = bn_beta[tid] - bn_mean[tid] * sc;
    }
    if (tid < 8) s_b3[tid] = (tid < 6) ? eb3[tid] : 0.f;
    if (tid < 8) s_dsum[tid] = 0.f;
    for (int i = tid; i < 304; i += BT) s_eff[i] = 0.f;
    __syncthreads();

    // ---- batchnorm ----
    const float* xb = x + b * 800;
    for (int i = tid; i < 800; i += BT) {
        int f = i & 15;
        s_xn[i] = fmaf(xb[i], s_bns[f], s_bnt[f]);
    }
    __syncthreads();

    // ---- factored edge layer 1: A[n]=xn[n]@W1_top+eb1, B[n]=xn[n]@W1_bot (row stride 31) ----
    for (int i = tid; i < 3000; i += BT) {
        int half = (i >= 1500);
        int idx  = half ? (i - 1500) : i;
        int n = idx / 30, k = idx - n * 30;
        const float* W = half ? s_W1b : s_W1a;
        float acc = half ? 0.f : s_eb1[k];
        const float* xr = s_xn + n * 16;
        #pragma unroll
        for (int f = 0; f < 16; f++) acc = fmaf(xr[f], W[f * 30 + k], acc);
        s_buf[(half ? 1550 : 0) + n * 31 + k] = acc;
    }
    __syncthreads();

    // ---- edge MLP, edge-parallel (e = j*50 + r so a warp hits 32 distinct receivers) ----
    #pragma unroll 1
    for (int e = tid; e < 2450; e += BT) {
        const int j = e / 50;
        const int r = e - j * 50;
        const int s = j + (j >= r);
        const float* Ar = s_buf + r * 31;
        const float* Bs = s_buf + 1550 + s * 31;

        float h2[16];
        #pragma unroll
        for (int q = 0; q < 16; q++) h2[q] = s_b2[q];

        #pragma unroll 5
        for (int i = 0; i < 30; i++) {
            float v = fmaxf(Ar[i] + Bs[i], 0.f);
            const float4* w = (const float4*)(s_W2 + i * 16);
            float4 w0 = w[0], w1 = w[1], w2 = w[2], w3 = w[3];
            h2[0]  = fmaf(v, w0.x, h2[0]);  h2[1]  = fmaf(v, w0.y, h2[1]);
            h2[2]  = fmaf(v, w0.z, h2[2]);  h2[3]  = fmaf(v, w0.w, h2[3]);
            h2[4]  = fmaf(v, w1.x, h2[4]);  h2[5]  = fmaf(v, w1.y, h2[5]);
            h2[6]  = fmaf(v, w1.z, h2[6]);  h2[7]  = fmaf(v, w1.w, h2[7]);
            h2[8]  = fmaf(v, w2.x, h2[8]);  h2[9]  = fmaf(v, w2.y, h2[9]);
            h2[10] = fmaf(v, w2.z, h2[10]); h2[11] = fmaf(v, w2.w, h2[11]);
            h2[12] = fmaf(v, w3.x, h2[12]); h2[13] = fmaf(v, w3.y, h2[13]);
            h2[14] = fmaf(v, w3.z, h2[14]); h2[15] = fmaf(v, w3.w, h2[15]);
        }

        float h3[6];
        #pragma unroll
        for (int m = 0; m < 6; m++) h3[m] = s_b3[m];

        #pragma unroll 4
        for (int q = 0; q < 16; q++) {
            float v = fmaxf(h2[q], 0.f);
            const float4* w = (const float4*)(s_W3 + q * 8);
            float4 wa = w[0], wb = w[1];
            h3[0] = fmaf(v, wa.x, h3[0]); h3[1] = fmaf(v, wa.y, h3[1]);
            h3[2] = fmaf(v, wa.z, h3[2]); h3[3] = fmaf(v, wa.w, h3[3]);
            h3[4] = fmaf(v, wb.x, h3[4]); h3[5] = fmaf(v, wb.y, h3[5]);
        }

        #pragma unroll
        for (int m = 0; m < 6; m++)
            atomicAdd(&s_eff[r * 6 + m], fmaxf(h3[m], 0.f));
    }
    __syncthreads();

    // ---- dynamics layer 1: [xn | eff] (22) -> 45 (reuse s_buf as d1) ----
    for (int i = tid; i < 2250; i += BT) {
        int n = i / 45, o = i - n * 45;
        float acc = s_db1[o];
        const float* xr = s_xn + n * 16;
        #pragma unroll
        for (int f = 0; f < 16; f++) acc = fmaf(xr[f], s_dW1[f * 45 + o], acc);
        const float* er = s_eff + n * 6;
        #pragma unroll
        for (int m = 0; m < 6; m++) acc = fmaf(er[m], s_dW1[(16 + m) * 45 + o], acc);
        s_buf[i] = fmaxf(acc, 0.f);
    }
    __syncthreads();

    // ---- dynamics layer 2: 45 -> 22 ----
    for (int i = tid; i < 1100; i += BT) {
        int n = i / 22, o = i - n * 22;
        float acc = s_db2[o];
        const float* dr = s_buf + n * 45;
        #pragma unroll 9
        for (int j = 0; j < 45; j++) acc = fmaf(dr[j], s_dW2[j * 22 + o], acc);
        s_d2[i] = fmaxf(acc, 0.f);
    }
    __syncthreads();

    // ---- dynamics layer 3: 22 -> 6, sum over nodes ----
    for (int i = tid; i < 300; i += BT) {
        int n = i / 6, o = i - n * 6;
        float acc = s_db3[o];
        const float* dr = s_d2 + n * 22;
        #pragma unroll 11
        for (int j = 0; j < 22; j++) acc = fmaf(dr[j], s_dW3[j * 6 + o], acc);
        atomicAdd(&s_dsum[o], fmaxf(acc, 0.f));
    }
    __syncthreads();

    // ---- classifier layer 1: 6 -> 48 ----
    if (tid < 48) {
        float acc = s_ab1[tid];
        #pragma unroll
        for (int j = 0; j < 6; j++) acc = fmaf(s_dsum[j], s_aW1[j * 48 + tid], acc);
        s_a1[tid] = fmaxf(acc, 0.f);
    }
    __syncthreads();

    // ---- classifier layer 2 + softmax ----
    if (tid == 0) {
        float lg[5];
        #pragma unroll
        for (int o = 0; o < 5; o++) {
            float acc = s_ab2[o];
            #pragma unroll
            for (int j = 0; j < 48; j++) acc = fmaf(s_a1[j], s_aW2[j * 5 + o], acc);
            lg[o] = acc;
        }
        float mx = lg[0];
        #pragma unroll
        for (int o = 1; o < 5; o++) mx = fmaxf(mx, lg[o]);
        float e[5], sum = 0.f;
        #pragma unroll
        for (int o = 0; o < 5; o++) { e[o] = expf(lg[o] - mx); sum += e[o]; }
        float inv = 1.f / sum;
        #pragma unroll
        for (int o = 0; o < 5; o++) out[b * 5 + o] = e[o] * inv;
    }
}

extern "C" void kernel_launch(void* const* d_in, const int* in_sizes, int n_in,
                              void* d_out, int out_size) {
    const int B = in_sizes[0] / 800;  // x is [B, 50, 16]
    convintnet_kernel<<<B, BT>>>(
        (const float*)d_in[0],
        (const float*)d_in[1],  (const float*)d_in[2],
        (const float*)d_in[3],  (const float*)d_in[4],
        (const float*)d_in[5],  (const float*)d_in[6],
        (const float*)d_in[7],  (const float*)d_in[8],
        (const float*)d_in[9],  (const float*)d_in[10],
        (const float*)d_in[11], (const float*)d_in[12],
        (const float*)d_in[13], (const float*)d_in[14],
        (const float*)d_in[15], (const float*)d_in[16],
        (const float*)d_in[17], (const float*)d_in[18],
        (const float*)d_in[19], (const float*)d_in[20],
        (float*)d_out);
}